// round 6
// baseline (speedup 1.0000x reference)
#include <cuda_runtime.h>
#include <cstdint>

// YoloV3Decoder: predictions (1, 145152, 85) fp32 -> tuple flattened as fp32:
//   [0 .. 4N)    bboxes (x,y,w,h)
//   [4N .. 5N)   scores
//   [5N .. 6N)   class_pred (as float)
//   [6N .. 12N)  detections (x,y,w,h,class_conf,class_pred)
// score_threshold input is unused by the reference outputs.

#define NUM_ANCHORS 145152
#define NUM_CH 85
#define ROWS 64
#define THREADS 256
#define NTILES (NUM_ANCHORS / ROWS)        // 2268
#define GRID 740                           // 148 SMs * 5 resident CTAs
#define TILE_F4 (ROWS * NUM_CH / 4)        // 1360 float4 per tile

__device__ __forceinline__ void cp_async16(uint32_t dst_s, const void* src)
{
    asm volatile("cp.async.cg.shared.global [%0], [%1], 16;"
                 :: "r"(dst_s), "l"(src) : "memory");
}
__device__ __forceinline__ void cp_commit()
{
    asm volatile("cp.async.commit_group;" ::: "memory");
}
__device__ __forceinline__ void cp_wait1()
{
    asm volatile("cp.async.wait_group 1;" ::: "memory");
}

__global__ __launch_bounds__(THREADS, 5) void yolo_decode_kernel(
    const float* __restrict__ pred, float* __restrict__ out)
{
    __shared__ float buf[2][ROWS * NUM_CH];   // 2 x 21760 B
    __shared__ float det_s[ROWS * 6];         // 1536 B

    const int tid = threadIdx.x;
    const uint32_t buf_s[2] = {
        (uint32_t)__cvta_generic_to_shared(&buf[0][0]),
        (uint32_t)__cvta_generic_to_shared(&buf[1][0])
    };

    const int t0 = blockIdx.x;

    // Issue all of a tile's loads for stage s (distributed over all threads).
    auto issue_tile = [&](int s, int t) {
        const float4* __restrict__ src =
            reinterpret_cast<const float4*>(pred + (size_t)t * ROWS * NUM_CH);
        const uint32_t dst = buf_s[s];
        #pragma unroll 6
        for (int i = tid; i < TILE_F4; i += THREADS) {
            cp_async16(dst + (uint32_t)i * 16u, src + i);
        }
    };

    // Prologue: fill both stages (commit even when empty to keep counts uniform).
    issue_tile(0, t0);
    cp_commit();
    if (t0 + GRID < NTILES) issue_tile(1, t0 + GRID);
    cp_commit();

    const int r = tid >> 2;        // local row 0..63
    const int q = tid & 3;         // quarter: 20 classes each
    const int cbase = q * 20;

    int it = 0;
    for (int t = t0; t < NTILES; t += GRID, ++it) {
        const int s = it & 1;

        cp_wait1();        // this thread's stage-s ops complete
        __syncthreads();   // everyone's ops complete -> tile visible

        const float* __restrict__ row = &buf[s][0] + r * NUM_CH;
        const int a = t * ROWS + r;    // global anchor

        // Local argmax over [cbase, cbase+20)
        float cmax = row[5 + cbase];
        int   cidx = cbase;
        #pragma unroll
        for (int c = 1; c < 20; ++c) {
            const float v = row[5 + cbase + c];
            if (v > cmax) { cmax = v; cidx = cbase + c; }
        }
        // Combine across the quad (lanes tid^1, tid^2 in-warp).
        #pragma unroll
        for (int d = 1; d <= 2; d <<= 1) {
            const float om = __shfl_xor_sync(0xFFFFFFFFu, cmax, d);
            const int   oi = __shfl_xor_sync(0xFFFFFFFFu, cidx, d);
            if (om > cmax || (om == cmax && oi < cidx)) { cmax = om; cidx = oi; }
        }
        const float cls_f = (float)cidx;

        if (q == 0) {
            const float inv = 1.0f / 1536.0f;
            const float bx = row[0] * inv;
            const float by = row[1] * inv;
            const float bw = row[2] * inv;
            const float bh = row[3] * inv;
            const float x = bx - bw * 0.5f;
            const float y = by - bh * 0.5f;
            const float w = bx + bw * 0.5f;
            const float h = by + bh * 0.5f;
            reinterpret_cast<float4*>(out)[a] = make_float4(x, y, w, h);
            float* __restrict__ d = det_s + r * 6;
            d[0] = x; d[1] = y; d[2] = w; d[3] = h;
            d[4] = cmax; d[5] = cls_f;
        } else if (q == 1) {
            const float obj = row[4];
            out[(size_t)NUM_ANCHORS * 4 + a] = obj * cmax;
        } else if (q == 2) {
            out[(size_t)NUM_ANCHORS * 5 + a] = cls_f;
        }

        __syncthreads();   // det_s written; all buf[s] reads finished

        // Coalesced detections: 64 rows * 6 floats = 96 float4
        if (tid < 96) {
            float4* __restrict__ det_g = reinterpret_cast<float4*>(
                out + (size_t)NUM_ANCHORS * 6 + (size_t)t * ROWS * 6);
            det_g[tid] = reinterpret_cast<const float4*>(det_s)[tid];
        }

        // Refill stage s for tile t + 2*GRID (buf[s] free after the barrier).
        const int tn = t + 2 * GRID;
        if (tn < NTILES) issue_tile(s, tn);
        cp_commit();       // always: uniform group count per thread
        // det_s overwrite next iteration is ordered by that iteration's
        // top-of-loop __syncthreads (det_g readers must arrive there first).
    }
}

extern "C" void kernel_launch(void* const* d_in, const int* in_sizes, int n_in,
                              void* d_out, int out_size)
{
    const float* pred = (const float*)d_in[0];
    // d_in[1] = score_threshold: unused by the reference outputs.
    float* out = (float*)d_out;

    yolo_decode_kernel<<<GRID, THREADS>>>(pred, out);
}